// round 1
// baseline (speedup 1.0000x reference)
#include <cuda_runtime.h>

// ---------------- problem constants ----------------
#define NYD 256
#define NXD 256
#define PML 20
#define PADW 22            // PML + 2
#define NP  300            // padded grid edge
#define NT  250
#define NSHOT 2
#define NSRC 8
#define NREC 64
#define DTC 0.0005f

// strips
#define SSTR 60            // strips per shot
#define RROW 5             // rows per strip
#define NCTA (NSHOT * SSTR)   // 120 CTAs  (<=148 SMs -> all resident, spin-sync safe)
#define BLOCK 320

// FD coefficients folded with 1/h and 1/h^2 (h = 5)
__device__ __constant__ float C1A =  1.0f/60.0f;   // w[y-2]
__device__ __constant__ float C1B = -2.0f/15.0f;   // w[y-1]
__device__ __constant__ float C1C =  2.0f/15.0f;   // w[y+1]
__device__ __constant__ float C1D = -1.0f/60.0f;   // w[y+2]
__device__ __constant__ float C2A = -1.0f/300.0f;  // +-2
__device__ __constant__ float C2B =  4.0f/75.0f;   // +-1
__device__ __constant__ float C2C = -0.1f;         // center

// ---------------- persistent device state ----------------
__device__ float g_wf  [2][NSHOT][NP][NP];
__device__ float g_psiy[2][NSHOT][NP][NP];
__device__ float g_psix[2][NSHOT][NP][NP];
__device__ float g_v2dt2[NP][NP];
__device__ float g_a[NP], g_b[NP];
__device__ int   g_sy[NSHOT*NSRC], g_sx[NSHOT*NSRC];
__device__ float g_sscale[NSHOT*NSRC];
__device__ int   g_ry[NSHOT*NREC], g_rx[NSHOT*NREC];
__device__ volatile int g_flag[NCTA];

// ---------------- init kernels ----------------
__global__ void init_fields(const float* __restrict__ v)
{
    int idx = blockIdx.x * blockDim.x + threadIdx.x;
    int stride = gridDim.x * blockDim.x;

    float* wf = &g_wf[0][0][0][0];
    float* py = &g_psiy[0][0][0][0];
    float* px = &g_psix[0][0][0][0];
    const int NSTATE = 2 * NSHOT * NP * NP;
    for (int i = idx; i < NSTATE; i += stride) { wf[i] = 0.f; py[i] = 0.f; px[i] = 0.f; }

    for (int i = idx; i < NP * NP; i += stride) {
        int y = i / NP, x = i - y * NP;
        int vy = min(max(y - PADW, 0), NYD - 1);
        int vx = min(max(x - PADW, 0), NXD - 1);
        float vv = v[vy * NXD + vx];
        (&g_v2dt2[0][0])[i] = vv * vv * (DTC * DTC);
    }

    for (int i = idx; i < NP; i += stride) {
        double fi = (double)i;
        double frac = fmax(22.0 - fi, fi - 277.0) / (double)PML;
        frac = fmin(fmax(frac, 0.0), 1.0);
        double sm   = 3.0 * 4000.0 * log(1000.0) / (2.0 * PML * 5.0);
        double sig  = sm * frac * frac;
        double alp  = 3.141592653589793 * 25.0 * (1.0 - frac);
        double bb   = exp(-(sig + alp) * (double)DTC);
        double aa   = sig / (sig + alp + 1e-9) * (bb - 1.0);
        g_a[i] = (float)aa;
        g_b[i] = (float)bb;
    }

    for (int i = idx; i < NCTA; i += stride) g_flag[i] = 0;
}

// Detect int64 vs int32 location buffers at runtime: int64 little-endian view
// as int32 gives [val,0,val,0,...]; legit int32 data has random x coords in the
// odd slots (P(all zero) ~ (1/256)^16 ~ 0).
__global__ void init_locs(const int* __restrict__ sl, const int* __restrict__ rl)
{
    if (threadIdx.x != 0 || blockIdx.x != 0) return;

    bool s64 = true;
    for (int k = 1; k < NSHOT * NSRC * 2; k += 2) if (sl[k] != 0) { s64 = false; break; }
    for (int s = 0; s < NSHOT * NSRC; s++) {
        int y = s64 ? sl[4*s]     : sl[2*s];
        int x = s64 ? sl[4*s + 2] : sl[2*s + 1];
        g_sy[s] = y + PADW; g_sx[s] = x + PADW;
        g_sscale[s] = g_v2dt2[y + PADW][x + PADW];
    }

    bool r64 = true;
    for (int k = 1; k < NSHOT * NREC * 2; k += 2) if (rl[k] != 0) { r64 = false; break; }
    for (int s = 0; s < NSHOT * NREC; s++) {
        int y = r64 ? rl[4*s]     : rl[2*s];
        int x = r64 ? rl[4*s + 2] : rl[2*s + 1];
        g_ry[s] = y + PADW; g_rx[s] = x + PADW;
    }
}

// ---------------- persistent wave kernel ----------------
__global__ void __launch_bounds__(BLOCK, 1)
wave_kernel(const float* __restrict__ amp, float* __restrict__ out)
{
    const int bid   = blockIdx.x;
    const int shot  = bid / SSTR;
    const int strip = bid - shot * SSTR;
    const int y0    = strip * RROW;
    const int tid   = threadIdx.x;
    const int c     = tid;
    const bool act  = (c < NP);
    const int cc    = c + 2;

    __shared__ float s_w [RROW + 8][NP + 4];
    __shared__ float s_py[RROW + 4][NP + 4];
    __shared__ float s_px[RROW + 4][NP + 4];
    __shared__ int   s_nsrc, s_nrec;
    __shared__ int   s_src_r[NSRC], s_src_c[NSRC], s_src_idx[NSRC];
    __shared__ float s_src_scale[NSRC];
    __shared__ short s_rec_r[NREC], s_rec_c[NREC];
    __shared__ int   s_rec_out[NREC];

    // zero guard columns (Dirichlet boundary in x)
    if (tid < RROW + 8) { s_w[tid][0] = 0.f; s_w[tid][1] = 0.f; s_w[tid][NP+2] = 0.f; s_w[tid][NP+3] = 0.f; }
    if (tid < RROW + 4) {
        s_py[tid][0] = 0.f; s_py[tid][1] = 0.f; s_py[tid][NP+2] = 0.f; s_py[tid][NP+3] = 0.f;
        s_px[tid][0] = 0.f; s_px[tid][1] = 0.f; s_px[tid][NP+2] = 0.f; s_px[tid][NP+3] = 0.f;
    }

    if (tid == 0) {
        int ns = 0;
        for (int i = 0; i < NSRC; i++) {
            int s = shot * NSRC + i;
            int r = g_sy[s] - y0;
            if (r >= 0 && r < RROW) {
                s_src_r[ns] = r; s_src_c[ns] = g_sx[s];
                s_src_idx[ns] = s; s_src_scale[ns] = g_sscale[s]; ns++;
            }
        }
        s_nsrc = ns;
        int nr = 0;
        for (int i = 0; i < NREC; i++) {
            int s = shot * NREC + i;
            int r = g_ry[s] - y0;
            if (r >= 0 && r < RROW) {
                s_rec_r[nr] = (short)r; s_rec_c[nr] = (short)g_rx[s];
                s_rec_out[nr] = s * NT; nr++;
            }
        }
        s_nrec = nr;
    }

    // per-thread register-resident state (column c, rows y0..y0+RROW-1)
    float wc[RROW] = {0.f,0.f,0.f,0.f,0.f};   // current wavefield
    float wm[RROW] = {0.f,0.f,0.f,0.f,0.f};   // previous wavefield
    float zy[RROW] = {0.f,0.f,0.f,0.f,0.f};   // zeta_y (never touches memory)
    float zx[RROW] = {0.f,0.f,0.f,0.f,0.f};   // zeta_x
    float v2[RROW];
    float ar[RROW + 4], br[RROW + 4];
    float axc = 0.f, bxc = 0.f;
    if (act) {
        axc = g_a[c]; bxc = g_b[c];
        #pragma unroll
        for (int r = 0; r < RROW; r++) v2[r] = g_v2dt2[y0 + r][c];
        #pragma unroll
        for (int j = 0; j < RROW + 4; j++) {
            int y = y0 - 2 + j;
            bool in = (y >= 0 && y < NP);
            ar[j] = in ? g_a[y] : 0.f;
            br[j] = in ? g_b[y] : 0.f;
        }
    }
    __syncthreads();

    for (int t = 0; t < NT; t++) {
        const int p = t & 1;
        const float* __restrict__ pyo  = &g_psiy[p][shot][0][0];
        const float* __restrict__ pxo  = &g_psix[p][shot][0][0];
        float* __restrict__ pyn        = &g_psiy[1 - p][shot][0][0];
        float* __restrict__ pxn        = &g_psix[1 - p][shot][0][0];
        const float* __restrict__ wfcg = &g_wf[p][shot][0][0];
        float* __restrict__ wfn        = &g_wf[1 - p][shot][0][0];

        // --- neighbor dataflow wait (acquire) ---
        if (tid == 0) {
            if (strip > 0)        while (g_flag[bid - 1] < t) { }
            if (strip < SSTR - 1) while (g_flag[bid + 1] < t) { }
            __threadfence();
        }
        __syncthreads();

        // --- stage wfc rows y0-4 .. y0+RROW+3 into smem ---
        if (act) {
            #pragma unroll
            for (int j = 0; j < 4; j++) {
                int y = y0 - 4 + j;
                s_w[j][cc] = (y >= 0) ? wfcg[y * NP + c] : 0.f;
            }
            #pragma unroll
            for (int r = 0; r < RROW; r++) s_w[4 + r][cc] = wc[r];
            #pragma unroll
            for (int j = 0; j < 4; j++) {
                int y = y0 + RROW + j;
                s_w[4 + RROW + j][cc] = (y < NP) ? wfcg[y * NP + c] : 0.f;
            }
        }
        __syncthreads();

        // --- phase A: psi on rows y0-2 .. y0+RROW+1 (2-row redundant halo) ---
        if (act) {
            float wm2 = s_w[0][cc], wm1 = s_w[1][cc], w0 = s_w[2][cc], wp1 = s_w[3][cc];
            #pragma unroll
            for (int j = 0; j < RROW + 4; j++) {
                float wp2 = s_w[j + 4][cc];
                int y = y0 - 2 + j;
                float pys = 0.f, pxs = 0.f;
                if (y >= 0 && y < NP) {
                    float dwdy = C1A*wm2 + C1B*wm1 + C1C*wp1 + C1D*wp2;
                    float dwdx = C1A*s_w[j+2][cc-2] + C1B*s_w[j+2][cc-1]
                               + C1C*s_w[j+2][cc+1] + C1D*s_w[j+2][cc+2];
                    pys = br[j] * pyo[y * NP + c] + ar[j] * dwdy;
                    pxs = bxc   * pxo[y * NP + c] + axc   * dwdx;
                    if (j >= 2 && j < 2 + RROW) {   // publish own rows only
                        pyn[y * NP + c] = pys;
                        pxn[y * NP + c] = pxs;
                    }
                }
                s_py[j][cc] = pys;
                s_px[j][cc] = pxs;
                wm2 = wm1; wm1 = w0; w0 = wp1; wp1 = wp2;
            }
        }
        __syncthreads();

        // --- phase B: zeta + wavefield update on own rows ---
        if (act) {
            float q0 = s_w[2][cc], q1 = s_w[3][cc], q2 = s_w[4][cc], q3 = s_w[5][cc];
            float p0 = s_py[0][cc], p1 = s_py[1][cc], p2 = s_py[2][cc], p3 = s_py[3][cc];
            const int ns = s_nsrc;
            #pragma unroll
            for (int r = 0; r < RROW; r++) {
                float q4 = s_w[r + 6][cc];
                float p4 = s_py[r + 4][cc];
                float d2y = C2A*q0 + C2B*q1 + C2C*q2 + C2B*q3 + C2A*q4;
                float d2x = C2A*s_w[r+4][cc-2] + C2B*s_w[r+4][cc-1] + C2C*q2
                          + C2B*s_w[r+4][cc+1] + C2A*s_w[r+4][cc+2];
                float dpy = C1A*p0 + C1B*p1 + C1C*p3 + C1D*p4;
                float dpx = C1A*s_px[r+2][cc-2] + C1B*s_px[r+2][cc-1]
                          + C1C*s_px[r+2][cc+1] + C1D*s_px[r+2][cc+2];
                float nzy = br[r + 2] * zy[r] + ar[r + 2] * (d2y + dpy);
                float nzx = bxc * zx[r] + axc * (d2x + dpx);
                zy[r] = nzy; zx[r] = nzx;
                float lap = d2y + d2x + dpy + dpx + nzy + nzx;
                float wp = 2.0f * wc[r] - wm[r] + v2[r] * lap;
                for (int k = 0; k < ns; k++)
                    if (s_src_c[k] == c && s_src_r[k] == r)
                        wp += s_src_scale[k] * amp[s_src_idx[k] * NT + t];
                wfn[(y0 + r) * NP + c] = wp;
                wm[r] = wc[r]; wc[r] = wp;
                q0 = q1; q1 = q2; q2 = q3; q3 = q4;
                p0 = p1; p1 = p2; p2 = p3; p3 = p4;
                (void)p2;
            }
        }
        __syncthreads();

        // --- publish completion (release) ---
        if (tid == 0) { __threadfence(); g_flag[bid] = t + 1; }

        // --- record receivers owned by this strip (post-source wfp) ---
        for (int k = tid; k < s_nrec; k += BLOCK)
            out[s_rec_out[k] + t] = wfn[(y0 + s_rec_r[k]) * NP + s_rec_c[k]];
    }
}

// ---------------- launch ----------------
extern "C" void kernel_launch(void* const* d_in, const int* in_sizes, int n_in,
                              void* d_out, int out_size)
{
    const float* v   = (const float*)d_in[0];
    const float* amp = (const float*)d_in[1];
    const int*   sl  = (const int*)d_in[2];
    const int*   rl  = (const int*)d_in[3];

    init_fields<<<NCTA, BLOCK>>>(v);
    init_locs<<<1, 32>>>(sl, rl);
    wave_kernel<<<NCTA, BLOCK>>>(amp, (float*)d_out);
}

// round 2
// speedup vs baseline: 1.3804x; 1.3804x over previous
#include <cuda_runtime.h>

// ---------------- problem constants ----------------
#define NYD 256
#define NXD 256
#define PML 20
#define PADW 22            // PML + FD_PAD
#define NP  300            // padded grid edge
#define NT  250
#define NSHOT 2
#define NSRC 8
#define NREC 64
#define DTC 0.0005f

// strips
#define SSTR 60            // strips per shot
#define RROW 5             // rows per strip
#define NCTA (NSHOT * SSTR)   // 120 CTAs  (<=148 SMs -> all resident, spin-sync safe)
#define BX 320
#define BY 2
#define NTHR (BX*BY)
#define NPX (NP + 4)

// FD coefficients folded with 1/h and 1/h^2 (h = 5)
#define C1A ( 1.0f/60.0f)
#define C1B (-2.0f/15.0f)
#define C1C ( 2.0f/15.0f)
#define C1D (-1.0f/60.0f)
#define C2A (-1.0f/300.0f)
#define C2B ( 4.0f/75.0f)
#define C2C (-0.1f)

// ---------------- persistent device state ----------------
__device__ float g_wf  [2][NSHOT][NP][NP];
__device__ float g_psiy[2][NSHOT][NP][NP];   // only halo rows (0,1,3,4 per strip) are live
__device__ float g_psix[2][NSHOT][NP][NP];
__device__ float g_v2dt2[NP][NP];
__device__ float g_a[NP], g_b[NP];
__device__ int   g_sy[NSHOT*NSRC], g_sx[NSHOT*NSRC];
__device__ float g_sscale[NSHOT*NSRC];
__device__ int   g_ry[NSHOT*NREC], g_rx[NSHOT*NREC];
__device__ int   g_flag[NCTA];

// ---------------- scoped sync helpers ----------------
__device__ __forceinline__ int poll_flag(const int* p) {
    int v; asm volatile("ld.acquire.gpu.b32 %0, [%1];" : "=r"(v) : "l"(p)); return v;
}
__device__ __forceinline__ void set_flag(int* p, int v) {
    asm volatile("st.release.gpu.b32 [%0], %1;" :: "l"(p), "r"(v) : "memory");
}

// ---------------- init kernel (single launch) ----------------
__global__ void init_all(const float* __restrict__ v,
                         const int* __restrict__ sl, const int* __restrict__ rl)
{
    int idx = blockIdx.x * blockDim.x + threadIdx.x;
    int stride = gridDim.x * blockDim.x;

    float* wf = &g_wf[0][0][0][0];
    float* py = &g_psiy[0][0][0][0];
    float* px = &g_psix[0][0][0][0];
    const int NSTATE = 2 * NSHOT * NP * NP;
    for (int i = idx; i < NSTATE; i += stride) { wf[i] = 0.f; py[i] = 0.f; px[i] = 0.f; }

    for (int i = idx; i < NP * NP; i += stride) {
        int y = i / NP, x = i - y * NP;
        int vy = min(max(y - PADW, 0), NYD - 1);
        int vx = min(max(x - PADW, 0), NXD - 1);
        float vv = v[vy * NXD + vx];
        (&g_v2dt2[0][0])[i] = vv * vv * (DTC * DTC);
    }

    for (int i = idx; i < NP; i += stride) {
        double fi = (double)i;
        double frac = fmax(22.0 - fi, fi - 277.0) / (double)PML;
        frac = fmin(fmax(frac, 0.0), 1.0);
        double sm   = 3.0 * 4000.0 * log(1000.0) / (2.0 * PML * 5.0);
        double sig  = sm * frac * frac;
        double alp  = 3.141592653589793 * 25.0 * (1.0 - frac);
        double bb   = exp(-(sig + alp) * (double)DTC);
        double aa   = sig / (sig + alp + 1e-9) * (bb - 1.0);
        g_a[i] = (float)aa;
        g_b[i] = (float)bb;
    }

    for (int i = idx; i < NCTA; i += stride) g_flag[i] = 0;

    if (idx == 0) {
        // int64 vs int32 detect: int64-LE viewed as int32 -> odd words all zero.
        bool s64 = true;
        for (int k = 1; k < NSHOT * NSRC * 2; k += 2) if (sl[k] != 0) { s64 = false; break; }
        for (int s = 0; s < NSHOT * NSRC; s++) {
            int y = s64 ? sl[4*s]     : sl[2*s];
            int x = s64 ? sl[4*s + 2] : sl[2*s + 1];
            g_sy[s] = y + PADW; g_sx[s] = x + PADW;
            float vv = v[y * NXD + x];           // interior coords map 1:1 into padded grid
            g_sscale[s] = vv * vv * (DTC * DTC);
        }
        bool r64 = true;
        for (int k = 1; k < NSHOT * NREC * 2; k += 2) if (rl[k] != 0) { r64 = false; break; }
        for (int s = 0; s < NSHOT * NREC; s++) {
            int y = r64 ? rl[4*s]     : rl[2*s];
            int x = r64 ? rl[4*s + 2] : rl[2*s + 1];
            g_ry[s] = y + PADW; g_rx[s] = x + PADW;
        }
    }
}

// ---------------- persistent wave kernel ----------------
// Block = (320, 2): ty=0 owns strip rows 0..2 (psi rows j=0..4),
//                   ty=1 owns strip rows 3..4 (psi rows j=5..8).
__global__ void __launch_bounds__(NTHR, 1)
wave_kernel(const float* __restrict__ amp, float* __restrict__ out)
{
    const int bid   = blockIdx.x;
    const int shot  = bid / SSTR;
    const int strip = bid - shot * SSTR;
    const int y0    = strip * RROW;
    const int c     = threadIdx.x;
    const int ty    = threadIdx.y;
    const int tidl  = threadIdx.x + BX * threadIdx.y;
    const bool act  = (c < NP);
    const int cc    = c + 2;

    const int jbase = ty * 5;            // first psi row handled
    const int nA    = ty ? 4 : 5;        // psi rows handled
    const int rbase = ty * 3;            // first owned strip row
    const int nB    = ty ? 2 : 3;        // owned strip rows

    __shared__ float s_w [13][NPX];      // wf rows y0-4 .. y0+8
    __shared__ float s_py[9][NPX];       // psi rows y0-2 .. y0+6
    __shared__ float s_px[9][NPX];
    __shared__ int   s_nsrc, s_nrec;
    __shared__ int   s_src_r[NSRC], s_src_c[NSRC], s_src_idx[NSRC];
    __shared__ float s_src_scale[NSRC];
    __shared__ short s_rec_r[NREC], s_rec_c[NREC];
    __shared__ int   s_rec_out[NREC];

    // zero guard columns (Dirichlet boundary in x)
    if (tidl < 13) { s_w[tidl][0] = 0.f; s_w[tidl][1] = 0.f; s_w[tidl][NP+2] = 0.f; s_w[tidl][NP+3] = 0.f; }
    if (tidl >= 16 && tidl < 25) {
        int r = tidl - 16;
        s_py[r][0] = 0.f; s_py[r][1] = 0.f; s_py[r][NP+2] = 0.f; s_py[r][NP+3] = 0.f;
        s_px[r][0] = 0.f; s_px[r][1] = 0.f; s_px[r][NP+2] = 0.f; s_px[r][NP+3] = 0.f;
    }

    if (tidl == 0) {
        int ns = 0;
        for (int i = 0; i < NSRC; i++) {
            int s = shot * NSRC + i;
            int r = g_sy[s] - y0;
            if (r >= 0 && r < RROW) {
                s_src_r[ns] = r; s_src_c[ns] = g_sx[s];
                s_src_idx[ns] = s; s_src_scale[ns] = g_sscale[s]; ns++;
            }
        }
        s_nsrc = ns;
        int nr = 0;
        for (int i = 0; i < NREC; i++) {
            int s = shot * NREC + i;
            int r = g_ry[s] - y0;
            if (r >= 0 && r < RROW) {
                s_rec_r[nr] = (short)r; s_rec_c[nr] = (short)g_rx[s];
                s_rec_out[nr] = s * NT; nr++;
            }
        }
        s_nrec = nr;
    }

    // per-thread register state for owned rows
    float wc[3] = {0.f,0.f,0.f};
    float wm[3] = {0.f,0.f,0.f};
    float zy[3] = {0.f,0.f,0.f};
    float zx[3] = {0.f,0.f,0.f};
    float pyr[3] = {0.f,0.f,0.f};   // psi_y state (owned rows)
    float pxr[3] = {0.f,0.f,0.f};
    float v2[3], arB[3], brB[3];
    float arA[5], brA[5];
    float axc = 0.f, bxc = 0.f;
    if (act) {
        axc = g_a[c]; bxc = g_b[c];
        #pragma unroll
        for (int i = 0; i < 3; i++) {
            int y = min(y0 + rbase + i, NP - 1);
            v2[i]  = g_v2dt2[y][c];
            arB[i] = g_a[y];
            brB[i] = g_b[y];
        }
        #pragma unroll
        for (int jj = 0; jj < 5; jj++) {
            int y = y0 - 2 + jbase + jj;
            bool in = (y >= 0 && y < NP);
            int yc = min(max(y, 0), NP - 1);
            arA[jj] = in ? g_a[yc] : 0.f;
            brA[jj] = in ? g_b[yc] : 0.f;
        }
    }
    __syncthreads();

    for (int t = 0; t < NT; t++) {
        const int p = t & 1;
        const float* __restrict__ pyo  = &g_psiy[p][shot][0][0];
        const float* __restrict__ pxo  = &g_psix[p][shot][0][0];
        float* __restrict__ pyn        = &g_psiy[1 - p][shot][0][0];
        float* __restrict__ pxn        = &g_psix[1 - p][shot][0][0];
        const float* __restrict__ wfcg = &g_wf[p][shot][0][0];
        float* __restrict__ wfn        = &g_wf[1 - p][shot][0][0];

        // --- neighbor dataflow wait (acquire) ---
        if (tidl == 0) {
            if (strip > 0)        while (poll_flag(&g_flag[bid - 1]) < t) { }
            if (strip < SSTR - 1) while (poll_flag(&g_flag[bid + 1]) < t) { }
        }
        __syncthreads();

        // --- stage wfc rows y0-4 .. y0+8 into smem ---
        if (act) {
            if (ty == 0) {
                #pragma unroll
                for (int j = 0; j < 4; j++) {
                    int y = y0 - 4 + j;
                    s_w[j][cc] = (y >= 0) ? __ldcg(&wfcg[y * NP + c]) : 0.f;
                }
                #pragma unroll
                for (int i = 0; i < 3; i++) s_w[4 + i][cc] = wc[i];
            } else {
                #pragma unroll
                for (int i = 0; i < 2; i++) s_w[7 + i][cc] = wc[i];
                #pragma unroll
                for (int j = 0; j < 4; j++) {
                    int y = y0 + RROW + j;
                    s_w[9 + j][cc] = (y < NP) ? __ldcg(&wfcg[y * NP + c]) : 0.f;
                }
            }
        }
        __syncthreads();

        // --- phase A: psi on rows j = jbase .. jbase+nA-1  (y = y0-2+j) ---
        if (act) {
            float w0 = s_w[jbase + 0][cc];
            float w1 = s_w[jbase + 1][cc];
            float w2 = s_w[jbase + 2][cc];
            float w3 = s_w[jbase + 3][cc];
            #pragma unroll
            for (int jj = 0; jj < 5; jj++) {
                if (jj < nA) {
                    int j = jbase + jj;
                    float w4 = s_w[j + 4][cc];
                    int y = y0 - 2 + j;
                    float pys = 0.f, pxs = 0.f;
                    if (y >= 0 && y < NP) {
                        float dwdy = C1A*w0 + C1B*w1 + C1C*w3 + C1D*w4;
                        float dwdx = C1A*s_w[j+2][cc-2] + C1B*s_w[j+2][cc-1]
                                   + C1C*s_w[j+2][cc+1] + C1D*s_w[j+2][cc+2];
                        bool own = (ty == 0) ? (jj >= 2) : (jj < 2);
                        int oi = (ty == 0) ? (jj - 2) : jj;
                        float pyold, pxold;
                        if (own) { pyold = pyr[oi]; pxold = pxr[oi]; }
                        else     { pyold = __ldcg(&pyo[y * NP + c]);
                                   pxold = __ldcg(&pxo[y * NP + c]); }
                        pys = brA[jj] * pyold + arA[jj] * dwdy;
                        pxs = bxc * pxold + axc * dwdx;
                        if (own) {
                            pyr[oi] = pys; pxr[oi] = pxs;
                            // publish halo rows: strip rows 0,1 (g0) and 3,4 (g1)
                            bool pub = (ty == 0) ? (jj <= 3) : true;
                            if (pub) {
                                __stcg(&pyn[y * NP + c], pys);
                                __stcg(&pxn[y * NP + c], pxs);
                            }
                        }
                    }
                    s_py[j][cc] = pys;
                    s_px[j][cc] = pxs;
                    w0 = w1; w1 = w2; w2 = w3; w3 = w4;
                }
            }
        }
        __syncthreads();

        // --- phase B: zeta + wavefield update on owned rows ---
        if (act) {
            float q0 = s_w[rbase + 2][cc];
            float q1 = s_w[rbase + 3][cc];
            float q2 = s_w[rbase + 4][cc];
            float q3 = s_w[rbase + 5][cc];
            const int ns = s_nsrc;
            #pragma unroll
            for (int i = 0; i < 3; i++) {
                if (i < nB) {
                    int r = rbase + i;
                    float q4 = s_w[r + 6][cc];
                    float d2y = C2A*q0 + C2B*q1 + C2C*q2 + C2B*q3 + C2A*q4;
                    float d2x = C2A*s_w[r+4][cc-2] + C2B*s_w[r+4][cc-1] + C2C*q2
                              + C2B*s_w[r+4][cc+1] + C2A*s_w[r+4][cc+2];
                    float dpy = C1A*s_py[r][cc] + C1B*s_py[r+1][cc]
                              + C1C*s_py[r+3][cc] + C1D*s_py[r+4][cc];
                    float dpx = C1A*s_px[r+2][cc-2] + C1B*s_px[r+2][cc-1]
                              + C1C*s_px[r+2][cc+1] + C1D*s_px[r+2][cc+2];
                    float nzy = brB[i] * zy[i] + arB[i] * (d2y + dpy);
                    float nzx = bxc * zx[i] + axc * (d2x + dpx);
                    zy[i] = nzy; zx[i] = nzx;
                    float lap = d2y + d2x + dpy + dpx + nzy + nzx;
                    float wp = 2.0f * wc[i] - wm[i] + v2[i] * lap;
                    for (int k = 0; k < ns; k++)
                        if (s_src_c[k] == c && s_src_r[k] == r)
                            wp += s_src_scale[k] * amp[s_src_idx[k] * NT + t];
                    __stcg(&wfn[(y0 + r) * NP + c], wp);
                    wm[i] = wc[i]; wc[i] = wp;
                    q0 = q1; q1 = q2; q2 = q3; q3 = q4;
                }
            }
        }
        __syncthreads();

        // --- publish completion (release: orders the .cg stores above) ---
        if (tidl == 0) set_flag(&g_flag[bid], t + 1);

        // --- record receivers owned by this strip (post-source wfp) ---
        for (int k = tidl; k < s_nrec; k += NTHR)
            out[s_rec_out[k] + t] = __ldcg(&wfn[(y0 + s_rec_r[k]) * NP + s_rec_c[k]]);
    }
}

// ---------------- launch ----------------
extern "C" void kernel_launch(void* const* d_in, const int* in_sizes, int n_in,
                              void* d_out, int out_size)
{
    const float* v   = (const float*)d_in[0];
    const float* amp = (const float*)d_in[1];
    const int*   sl  = (const int*)d_in[2];
    const int*   rl  = (const int*)d_in[3];

    init_all<<<NCTA, 256>>>(v, sl, rl);
    dim3 blk(BX, BY);
    wave_kernel<<<NCTA, blk>>>(amp, (float*)d_out);
}

// round 5
// speedup vs baseline: 1.7915x; 1.2978x over previous
#include <cuda_runtime.h>

// ---------------- problem constants ----------------
#define NYD 256
#define NXD 256
#define PML 20
#define PADW 22            // PML + FD_PAD
#define NP  300            // padded grid edge
#define NT  250
#define NSHOT 2
#define NSRC 8
#define NREC 64
#define DTC 0.0005f

// strips
#define SSTR 60            // strips per shot
#define RROW 5             // rows per strip
#define NCTA (NSHOT * SSTR)   // 120 CTAs (<=148 SMs -> all resident, spin-sync safe)
#define BX 320
#define BY 3
#define NTHR (BX*BY)       // 960 threads, 30 warps  (<=1024!)
#define NPX (NP + 4)

// FD coefficients folded with 1/h and 1/h^2 (h = 5)
#define C1A ( 1.0f/60.0f)
#define C1B (-2.0f/15.0f)
#define C1C ( 2.0f/15.0f)
#define C1D (-1.0f/60.0f)
#define C2A (-1.0f/300.0f)
#define C2B ( 4.0f/75.0f)
#define C2C (-0.1f)

// ---------------- persistent device state ----------------
__device__ float g_wf  [2][NSHOT][NP][NP];
__device__ float g_psiy[2][NSHOT][NP][NP];   // only halo rows (0,1,3,4 per strip) live
__device__ float g_psix[2][NSHOT][NP][NP];
__device__ float g_v2dt2[NP][NP];
__device__ float g_a[NP], g_b[NP];
__device__ int   g_sy[NSHOT*NSRC], g_sx[NSHOT*NSRC];
__device__ float g_sscale[NSHOT*NSRC];
__device__ int   g_ry[NSHOT*NREC], g_rx[NSHOT*NREC];
__device__ int   g_flag[NCTA * 32];          // 128B-padded flags

// ---------------- scoped sync helpers ----------------
__device__ __forceinline__ int poll_flag(const int* p) {
    int v; asm volatile("ld.acquire.gpu.b32 %0, [%1];" : "=r"(v) : "l"(p)); return v;
}
__device__ __forceinline__ void set_flag(int* p, int v) {
    asm volatile("st.release.gpu.b32 [%0], %1;" :: "l"(p), "r"(v) : "memory");
}

// ---------------- init kernel (single launch) ----------------
__global__ void init_all(const float* __restrict__ v,
                         const int* __restrict__ sl, const int* __restrict__ rl)
{
    int idx = blockIdx.x * blockDim.x + threadIdx.x;
    int stride = gridDim.x * blockDim.x;

    float* wf = &g_wf[0][0][0][0];
    float* py = &g_psiy[0][0][0][0];
    float* px = &g_psix[0][0][0][0];
    const int NSTATE = 2 * NSHOT * NP * NP;
    for (int i = idx; i < NSTATE; i += stride) { wf[i] = 0.f; py[i] = 0.f; px[i] = 0.f; }

    for (int i = idx; i < NP * NP; i += stride) {
        int y = i / NP, x = i - y * NP;
        int vy = min(max(y - PADW, 0), NYD - 1);
        int vx = min(max(x - PADW, 0), NXD - 1);
        float vv = v[vy * NXD + vx];
        (&g_v2dt2[0][0])[i] = vv * vv * (DTC * DTC);
    }

    for (int i = idx; i < NP; i += stride) {
        double fi = (double)i;
        double frac = fmax(22.0 - fi, fi - 277.0) / (double)PML;
        frac = fmin(fmax(frac, 0.0), 1.0);
        double sm   = 3.0 * 4000.0 * log(1000.0) / (2.0 * PML * 5.0);
        double sig  = sm * frac * frac;
        double alp  = 3.141592653589793 * 25.0 * (1.0 - frac);
        double bb   = exp(-(sig + alp) * (double)DTC);
        double aa   = sig / (sig + alp + 1e-9) * (bb - 1.0);
        g_a[i] = (float)aa;
        g_b[i] = (float)bb;
    }

    for (int i = idx; i < NCTA * 32; i += stride) g_flag[i] = 0;

    if (idx == 0) {
        // int64 vs int32 detect: int64-LE viewed as int32 -> odd words all zero.
        bool s64 = true;
        for (int k = 1; k < NSHOT * NSRC * 2; k += 2) if (sl[k] != 0) { s64 = false; break; }
        for (int s = 0; s < NSHOT * NSRC; s++) {
            int y = s64 ? sl[4*s]     : sl[2*s];
            int x = s64 ? sl[4*s + 2] : sl[2*s + 1];
            g_sy[s] = y + PADW; g_sx[s] = x + PADW;
            float vv = v[y * NXD + x];
            g_sscale[s] = vv * vv * (DTC * DTC);
        }
        bool r64 = true;
        for (int k = 1; k < NSHOT * NREC * 2; k += 2) if (rl[k] != 0) { r64 = false; break; }
        for (int s = 0; s < NSHOT * NREC; s++) {
            int y = r64 ? rl[4*s]     : rl[2*s];
            int x = r64 ? rl[4*s + 2] : rl[2*s + 1];
            g_ry[s] = y + PADW; g_rx[s] = x + PADW;
        }
    }
}

// ---------------- persistent wave kernel ----------------
// Block (320, 3).
// Phase A psi rows j (y = y0-2+j):  ty0: j0,1,2   ty1: j3,4,5   ty2: j6,7,8
//   psi register ownership (j=2..6 <-> strip rows 0..4): ty0 owns r0; ty1 r1-r3; ty2 r4.
// Phase B strip rows:               ty0: r0,r1   ty1: r2,r3   ty2: r4
__global__ void __launch_bounds__(NTHR, 1)
wave_kernel(const float* __restrict__ amp, float* __restrict__ out)
{
    const int bid   = blockIdx.x;
    const int shot  = bid / SSTR;
    const int strip = bid - shot * SSTR;
    const int y0    = strip * RROW;
    const int c     = threadIdx.x;
    const int ty    = threadIdx.y;
    const int tidl  = threadIdx.x + BX * threadIdx.y;
    const bool act  = (c < NP);
    const int cc    = c + 2;

    const int jb  = ty * 3;                            // first psi row
    const int ofs = (ty == 0) ? 2 : (ty == 1) ? 3 : 6; // first OWNED psi row j
    const int rb  = ty * 2;                            // first phase-B strip row
    const int nb  = (ty == 2) ? 1 : 2;

    __shared__ float s_w [13][NPX];      // wf rows y0-4 .. y0+8
    __shared__ float s_py[9][NPX];       // psi rows y0-2 .. y0+6
    __shared__ float s_px[9][NPX];
    __shared__ float s_v2[5][NPX];
    __shared__ float s_aA[9], s_bA[9];
    __shared__ int   s_nsrc, s_nrec;
    __shared__ int   s_src_r[NSRC], s_src_c[NSRC], s_src_idx[NSRC];
    __shared__ float s_src_scale[NSRC];
    __shared__ short s_rec_r[NREC], s_rec_c[NREC];
    __shared__ int   s_rec_out[NREC];

    // zero guard columns (Dirichlet boundary in x)
    if (tidl < 13) { s_w[tidl][0] = 0.f; s_w[tidl][1] = 0.f; s_w[tidl][NP+2] = 0.f; s_w[tidl][NP+3] = 0.f; }
    if (tidl >= 16 && tidl < 25) {
        int r = tidl - 16;
        s_py[r][0] = 0.f; s_py[r][1] = 0.f; s_py[r][NP+2] = 0.f; s_py[r][NP+3] = 0.f;
        s_px[r][0] = 0.f; s_px[r][1] = 0.f; s_px[r][NP+2] = 0.f; s_px[r][NP+3] = 0.f;
    }
    if (tidl >= 32 && tidl < 41) {
        int j = tidl - 32;
        int y = y0 - 2 + j;
        bool in = (y >= 0 && y < NP);
        s_aA[j] = in ? g_a[y] : 0.f;
        s_bA[j] = in ? g_b[y] : 0.f;
    }
    if (act) {
        #pragma unroll
        for (int i = 0; i < 2; i++)
            if (i < nb) s_v2[rb + i][cc] = g_v2dt2[y0 + rb + i][c];
    }

    if (tidl == 0) {
        int ns = 0;
        for (int i = 0; i < NSRC; i++) {
            int s = shot * NSRC + i;
            int r = g_sy[s] - y0;
            if (r >= 0 && r < RROW) {
                s_src_r[ns] = r; s_src_c[ns] = g_sx[s];
                s_src_idx[ns] = s; s_src_scale[ns] = g_sscale[s]; ns++;
            }
        }
        s_nsrc = ns;
        int nr = 0;
        for (int i = 0; i < NREC; i++) {
            int s = shot * NREC + i;
            int r = g_ry[s] - y0;
            if (r >= 0 && r < RROW) {
                s_rec_r[nr] = (short)r; s_rec_c[nr] = (short)g_rx[s];
                s_rec_out[nr] = s * NT; nr++;
            }
        }
        s_nrec = nr;
    }

    // per-thread register state
    float wc[2] = {0.f,0.f};     // phase-B owned wavefield rows
    float wm[2] = {0.f,0.f};
    float zy[2] = {0.f,0.f};
    float zx[2] = {0.f,0.f};
    float pyr[3] = {0.f,0.f,0.f};  // phase-A owned psi rows (ty1 owns 3)
    float pxr[3] = {0.f,0.f,0.f};
    float axc = 0.f, bxc = 0.f;
    if (act) { axc = g_a[c]; bxc = g_b[c]; }
    __syncthreads();

    for (int t = 0; t < NT; t++) {
        const int p = t & 1;
        const float* __restrict__ pyo  = &g_psiy[p][shot][0][0];
        const float* __restrict__ pxo  = &g_psix[p][shot][0][0];
        float* __restrict__ pyn        = &g_psiy[1 - p][shot][0][0];
        float* __restrict__ pxn        = &g_psix[1 - p][shot][0][0];
        const float* __restrict__ wfcg = &g_wf[p][shot][0][0];
        float* __restrict__ wfn        = &g_wf[1 - p][shot][0][0];

        // --- neighbor dataflow wait (acquire), lane-parallel ---
        if (tidl < 2) {
            bool need = tidl ? (strip < SSTR - 1) : (strip > 0);
            if (need) {
                const int* fp = &g_flag[(tidl ? bid + 1 : bid - 1) * 32];
                while (poll_flag(fp) < t) { }
            }
        }
        __syncthreads();

        // --- stage wf halo + own rows into smem; prefetch psi halo to regs ---
        float pyh[2] = {0.f,0.f}, pxh[2] = {0.f,0.f};
        if (act) {
            if (ty == 0) {
                #pragma unroll
                for (int j = 0; j < 4; j++) {
                    int y = y0 - 4 + j;
                    s_w[j][cc] = (y >= 0) ? __ldcg(&wfcg[y * NP + c]) : 0.f;
                }
                s_w[4][cc] = wc[0];
                s_w[5][cc] = wc[1];
                #pragma unroll
                for (int h = 0; h < 2; h++) {          // psi rows y0-2, y0-1
                    int y = y0 - 2 + h;
                    if (y >= 0) { pyh[h] = __ldcg(&pyo[y * NP + c]);
                                  pxh[h] = __ldcg(&pxo[y * NP + c]); }
                }
            } else if (ty == 1) {
                s_w[6][cc] = wc[0];
                s_w[7][cc] = wc[1];
            } else {
                s_w[8][cc] = wc[0];
                #pragma unroll
                for (int j = 0; j < 4; j++) {
                    int y = y0 + 5 + j;
                    s_w[9 + j][cc] = (y < NP) ? __ldcg(&wfcg[y * NP + c]) : 0.f;
                }
                #pragma unroll
                for (int h = 0; h < 2; h++) {          // psi rows y0+5, y0+6
                    int y = y0 + 5 + h;
                    if (y < NP) { pyh[h] = __ldcg(&pyo[y * NP + c]);
                                  pxh[h] = __ldcg(&pxo[y * NP + c]); }
                }
            }
        }
        __syncthreads();

        // --- phase A: psi rows j = jb .. jb+2 ---
        if (act) {
            float w0 = s_w[jb + 0][cc];
            float w1 = s_w[jb + 1][cc];
            float w2 = s_w[jb + 2][cc];
            float w3 = s_w[jb + 3][cc];
            #pragma unroll
            for (int jj = 0; jj < 3; jj++) {
                int j = jb + jj;
                float w4 = s_w[j + 4][cc];
                int y = y0 - 2 + j;
                float pys = 0.f, pxs = 0.f;
                if (y >= 0 && y < NP) {
                    float dwdy = C1A*w0 + C1B*w1 + C1C*w3 + C1D*w4;
                    float dwdx = C1A*s_w[j+2][cc-2] + C1B*s_w[j+2][cc-1]
                               + C1C*s_w[j+2][cc+1] + C1D*s_w[j+2][cc+2];
                    bool own = (j >= 2 && j <= 6);
                    float pyold, pxold;
                    if (own) { pyold = pyr[j - ofs]; pxold = pxr[j - ofs]; }
                    else {
                        int h = (ty == 0) ? jj : jj - 1;   // ty0: j0,1 ; ty2: j7,8
                        pyold = pyh[h]; pxold = pxh[h];
                    }
                    pys = s_bA[j] * pyold + s_aA[j] * dwdy;
                    pxs = bxc * pxold + axc * dwdx;
                    if (own) {
                        pyr[j - ofs] = pys; pxr[j - ofs] = pxs;
                        if (j != 4) {   // publish halo-visible strip rows 0,1,3,4
                            __stcg(&pyn[y * NP + c], pys);
                            __stcg(&pxn[y * NP + c], pxs);
                        }
                    }
                }
                s_py[j][cc] = pys;
                s_px[j][cc] = pxs;
                w0 = w1; w1 = w2; w2 = w3; w3 = w4;
            }
        }
        __syncthreads();

        // --- phase B: zeta + wavefield update on owned rows ---
        if (act) {
            float q0 = s_w[rb + 2][cc];
            float q1 = s_w[rb + 3][cc];
            float q2 = s_w[rb + 4][cc];
            float q3 = s_w[rb + 5][cc];
            const int ns = s_nsrc;
            #pragma unroll
            for (int ii = 0; ii < 2; ii++) {
                if (ii < nb) {
                    int r = rb + ii;
                    float q4 = s_w[r + 6][cc];
                    float d2y = C2A*q0 + C2B*q1 + C2C*q2 + C2B*q3 + C2A*q4;
                    float d2x = C2A*s_w[r+4][cc-2] + C2B*s_w[r+4][cc-1] + C2C*q2
                              + C2B*s_w[r+4][cc+1] + C2A*s_w[r+4][cc+2];
                    float dpy = C1A*s_py[r][cc] + C1B*s_py[r+1][cc]
                              + C1C*s_py[r+3][cc] + C1D*s_py[r+4][cc];
                    float dpx = C1A*s_px[r+2][cc-2] + C1B*s_px[r+2][cc-1]
                              + C1C*s_px[r+2][cc+1] + C1D*s_px[r+2][cc+2];
                    float rA = s_aA[r + 2], rB = s_bA[r + 2];
                    float nzy = rB * zy[ii] + rA * (d2y + dpy);
                    float nzx = bxc * zx[ii] + axc * (d2x + dpx);
                    zy[ii] = nzy; zx[ii] = nzx;
                    float lap = d2y + d2x + dpy + dpx + nzy + nzx;
                    float wp = 2.0f * wc[ii] - wm[ii] + s_v2[r][cc] * lap;
                    for (int k = 0; k < ns; k++)
                        if (s_src_c[k] == c && s_src_r[k] == r)
                            wp += s_src_scale[k] * amp[s_src_idx[k] * NT + t];
                    __stcg(&wfn[(y0 + r) * NP + c], wp);
                    wm[ii] = wc[ii]; wc[ii] = wp;
                    q0 = q1; q1 = q2; q2 = q3; q3 = q4;
                }
            }
        }
        __syncthreads();

        // --- publish completion (release) ---
        if (tidl == 0) set_flag(&g_flag[bid * 32], t + 1);

        // --- record receivers owned by this strip ---
        for (int k = tidl; k < s_nrec; k += NTHR)
            out[s_rec_out[k] + t] = __ldcg(&wfn[(y0 + s_rec_r[k]) * NP + s_rec_c[k]]);
    }
}

// ---------------- launch ----------------
extern "C" void kernel_launch(void* const* d_in, const int* in_sizes, int n_in,
                              void* d_out, int out_size)
{
    const float* v   = (const float*)d_in[0];
    const float* amp = (const float*)d_in[1];
    const int*   sl  = (const int*)d_in[2];
    const int*   rl  = (const int*)d_in[3];

    init_all<<<NCTA, 256>>>(v, sl, rl);
    dim3 blk(BX, BY);
    wave_kernel<<<NCTA, blk>>>(amp, (float*)d_out);
}

// round 7
// speedup vs baseline: 2.3359x; 1.3039x over previous
#include <cuda_runtime.h>

// ---------------- problem constants ----------------
#define NYD 256
#define NXD 256
#define PML 20
#define PADW 22            // PML + FD_PAD
#define NP  300            // padded grid edge
#define NT  250
#define NSHOT 2
#define NSRC 8
#define NREC 64
#define DTC 0.0005f

// strips
#define SSTR 60            // strips per shot
#define RROW 5             // rows per strip
#define NCTA (NSHOT * SSTR)   // 120 CTAs (<=148 SMs -> all resident, spin-sync safe)
#define BX 320
#define BY 3
#define NTHR (BX*BY)       // 960 threads, 30 warps
#define NPX (NP + 4)

// FD coefficients folded with 1/h and 1/h^2 (h = 5)
#define C1A ( 1.0f/60.0f)
#define C1B (-2.0f/15.0f)
#define C1C ( 2.0f/15.0f)
#define C1D (-1.0f/60.0f)
#define C2A (-1.0f/300.0f)
#define C2B ( 4.0f/75.0f)
#define C2C (-0.1f)

// ---------------- persistent device state ----------------
// psi lives ONLY in registers now (each CTA redundantly maintains the psi
// recursion at its 4 halo rows from staged wf data -> bitwise identical).
__device__ float g_wf  [2][NSHOT][NP][NP];
__device__ float g_v2dt2[NP][NP];
__device__ float g_a[NP], g_b[NP];
__device__ int   g_sy[NSHOT*NSRC], g_sx[NSHOT*NSRC];
__device__ float g_sscale[NSHOT*NSRC];
__device__ int   g_ry[NSHOT*NREC], g_rx[NSHOT*NREC];
__device__ int   g_flag[NCTA * 32];          // 128B-padded flags

// ---------------- scoped sync helpers ----------------
__device__ __forceinline__ int poll_flag(const int* p) {
    int v; asm volatile("ld.acquire.gpu.b32 %0, [%1];" : "=r"(v) : "l"(p)); return v;
}
__device__ __forceinline__ void set_flag(int* p, int v) {
    asm volatile("st.release.gpu.b32 [%0], %1;" :: "l"(p), "r"(v) : "memory");
}

// ---------------- init kernel (single launch) ----------------
__global__ void init_all(const float* __restrict__ v,
                         const int* __restrict__ sl, const int* __restrict__ rl)
{
    int idx = blockIdx.x * blockDim.x + threadIdx.x;
    int stride = gridDim.x * blockDim.x;

    float* wf = &g_wf[0][0][0][0];
    const int NSTATE = 2 * NSHOT * NP * NP;
    for (int i = idx; i < NSTATE; i += stride) wf[i] = 0.f;

    for (int i = idx; i < NP * NP; i += stride) {
        int y = i / NP, x = i - y * NP;
        int vy = min(max(y - PADW, 0), NYD - 1);
        int vx = min(max(x - PADW, 0), NXD - 1);
        float vv = v[vy * NXD + vx];
        (&g_v2dt2[0][0])[i] = vv * vv * (DTC * DTC);
    }

    for (int i = idx; i < NP; i += stride) {
        double fi = (double)i;
        double frac = fmax(22.0 - fi, fi - 277.0) / (double)PML;
        frac = fmin(fmax(frac, 0.0), 1.0);
        double sm   = 3.0 * 4000.0 * log(1000.0) / (2.0 * PML * 5.0);
        double sig  = sm * frac * frac;
        double alp  = 3.141592653589793 * 25.0 * (1.0 - frac);
        double bb   = exp(-(sig + alp) * (double)DTC);
        double aa   = sig / (sig + alp + 1e-9) * (bb - 1.0);
        g_a[i] = (float)aa;
        g_b[i] = (float)bb;
    }

    for (int i = idx; i < NCTA * 32; i += stride) g_flag[i] = 0;

    if (idx == 0) {
        // int64 vs int32 detect: int64-LE viewed as int32 -> odd words all zero.
        bool s64 = true;
        for (int k = 1; k < NSHOT * NSRC * 2; k += 2) if (sl[k] != 0) { s64 = false; break; }
        for (int s = 0; s < NSHOT * NSRC; s++) {
            int y = s64 ? sl[4*s]     : sl[2*s];
            int x = s64 ? sl[4*s + 2] : sl[2*s + 1];
            g_sy[s] = y + PADW; g_sx[s] = x + PADW;
            float vv = v[y * NXD + x];
            g_sscale[s] = vv * vv * (DTC * DTC);
        }
        bool r64 = true;
        for (int k = 1; k < NSHOT * NREC * 2; k += 2) if (rl[k] != 0) { r64 = false; break; }
        for (int s = 0; s < NSHOT * NREC; s++) {
            int y = r64 ? rl[4*s]     : rl[2*s];
            int x = r64 ? rl[4*s + 2] : rl[2*s + 1];
            g_ry[s] = y + PADW; g_rx[s] = x + PADW;
        }
    }
}

// ---------------- persistent wave kernel ----------------
// Block (320, 3).
// Phase A psi rows j (y = y0-2+j):  ty0: j0,1,2   ty1: j3,4,5   ty2: j6,7,8
//   (ALL psi state register-resident, uniform ownership, zero global psi traffic)
// Phase B strip rows:               ty0: r0,r1   ty1: r2,r3   ty2: r4
__global__ void __launch_bounds__(NTHR, 1)
wave_kernel(const float* __restrict__ amp, float* __restrict__ out)
{
    const int bid   = blockIdx.x;
    const int shot  = bid / SSTR;
    const int strip = bid - shot * SSTR;
    const int y0    = strip * RROW;
    const int c     = threadIdx.x;
    const int ty    = threadIdx.y;
    const int tidl  = threadIdx.x + BX * threadIdx.y;
    const bool act  = (c < NP);
    const int cc    = c + 2;

    const int jb  = ty * 3;                // psi rows jb..jb+2 (register-owned)
    const int rb  = ty * 2;                // first phase-B strip row
    const int nb  = (ty == 2) ? 1 : 2;

    __shared__ float s_w [13][NPX];        // wf rows y0-4 .. y0+8
    __shared__ float s_py[9][NPX];         // psi rows y0-2 .. y0+6
    __shared__ float s_px[9][NPX];
    __shared__ float s_v2[5][NPX];
    __shared__ float s_aA[9], s_bA[9];
    __shared__ int   s_nsrc, s_nrec;
    __shared__ int   s_src_r[NSRC], s_src_c[NSRC], s_src_idx[NSRC];
    __shared__ float s_src_scale[NSRC];
    __shared__ short s_rec_r[NREC], s_rec_c[NREC];
    __shared__ int   s_rec_out[NREC];

    // zero guard columns (Dirichlet boundary in x)
    if (tidl < 13) { s_w[tidl][0] = 0.f; s_w[tidl][1] = 0.f; s_w[tidl][NP+2] = 0.f; s_w[tidl][NP+3] = 0.f; }
    if (tidl >= 16 && tidl < 25) {
        int r = tidl - 16;
        s_py[r][0] = 0.f; s_py[r][1] = 0.f; s_py[r][NP+2] = 0.f; s_py[r][NP+3] = 0.f;
        s_px[r][0] = 0.f; s_px[r][1] = 0.f; s_px[r][NP+2] = 0.f; s_px[r][NP+3] = 0.f;
    }
    if (tidl >= 32 && tidl < 41) {
        int j = tidl - 32;
        int y = y0 - 2 + j;
        bool in = (y >= 0 && y < NP);
        s_aA[j] = in ? g_a[y] : 0.f;
        s_bA[j] = in ? g_b[y] : 0.f;
    }
    if (act) {
        #pragma unroll
        for (int i = 0; i < 2; i++)
            if (i < nb) s_v2[rb + i][cc] = g_v2dt2[y0 + rb + i][c];
    }

    if (tidl == 0) {
        int ns = 0;
        for (int i = 0; i < NSRC; i++) {
            int s = shot * NSRC + i;
            int r = g_sy[s] - y0;
            if (r >= 0 && r < RROW) {
                s_src_r[ns] = r; s_src_c[ns] = g_sx[s];
                s_src_idx[ns] = s; s_src_scale[ns] = g_sscale[s]; ns++;
            }
        }
        s_nsrc = ns;
        int nr = 0;
        for (int i = 0; i < NREC; i++) {
            int s = shot * NREC + i;
            int r = g_ry[s] - y0;
            if (r >= 0 && r < RROW) {
                s_rec_r[nr] = (short)r; s_rec_c[nr] = (short)g_rx[s];
                s_rec_out[nr] = s * NT; nr++;
            }
        }
        s_nrec = nr;
    }

    // per-thread register state
    float wc[2]  = {0.f,0.f};      // phase-B owned wavefield rows
    float wm[2]  = {0.f,0.f};
    float zy[2]  = {0.f,0.f};
    float zx[2]  = {0.f,0.f};
    float pyr[3] = {0.f,0.f,0.f};  // phase-A owned psi rows (persistent)
    float pxr[3] = {0.f,0.f,0.f};
    float axc = 0.f, bxc = 0.f;
    if (act) { axc = g_a[c]; bxc = g_b[c]; }

    // parity-selected wf base pointers (hoisted out of the time loop)
    const float* wfb[2] = { &g_wf[0][shot][0][0], &g_wf[1][shot][0][0] };
    __syncthreads();

    for (int t = 0; t < NT; t++) {
        const int p = t & 1;
        const float* __restrict__ wfcg = wfb[p];
        float* __restrict__ wfn        = (float*)wfb[1 - p];

        // --- neighbor dataflow wait (acquire), lane-parallel ---
        if (tidl < 2) {
            bool need = tidl ? (strip < SSTR - 1) : (strip > 0);
            if (need) {
                const int* fp = &g_flag[(tidl ? bid + 1 : bid - 1) * 32];
                while (poll_flag(fp) < t) { }
            }
        }
        __syncthreads();

        // --- stage wf halo + own rows into smem ---
        if (act) {
            if (ty == 0) {
                #pragma unroll
                for (int j = 0; j < 4; j++) {
                    int y = y0 - 4 + j;
                    s_w[j][cc] = (y >= 0) ? __ldcg(&wfcg[y * NP + c]) : 0.f;
                }
                s_w[4][cc] = wc[0];
                s_w[5][cc] = wc[1];
            } else if (ty == 1) {
                s_w[6][cc] = wc[0];
                s_w[7][cc] = wc[1];
            } else {
                s_w[8][cc] = wc[0];
                #pragma unroll
                for (int j = 0; j < 4; j++) {
                    int y = y0 + 5 + j;
                    s_w[9 + j][cc] = (y < NP) ? __ldcg(&wfcg[y * NP + c]) : 0.f;
                }
            }
        }
        __syncthreads();

        // --- phase A: psi rows j = jb .. jb+2 (uniform, register recursion) ---
        if (act) {
            float w0 = s_w[jb + 0][cc];
            float w1 = s_w[jb + 1][cc];
            float w2 = s_w[jb + 2][cc];
            float w3 = s_w[jb + 3][cc];
            #pragma unroll
            for (int jj = 0; jj < 3; jj++) {
                int j = jb + jj;
                float w4 = s_w[j + 4][cc];
                int y = y0 - 2 + j;
                float pys = 0.f, pxs = 0.f;
                if (y >= 0 && y < NP) {
                    float dwdy = C1A*w0 + C1B*w1 + C1C*w3 + C1D*w4;
                    float dwdx = C1A*s_w[j+2][cc-2] + C1B*s_w[j+2][cc-1]
                               + C1C*s_w[j+2][cc+1] + C1D*s_w[j+2][cc+2];
                    pys = s_bA[j] * pyr[jj] + s_aA[j] * dwdy;
                    pxs = bxc * pxr[jj] + axc * dwdx;
                }
                pyr[jj] = pys; pxr[jj] = pxs;
                s_py[j][cc] = pys;
                s_px[j][cc] = pxs;
                w0 = w1; w1 = w2; w2 = w3; w3 = w4;
            }
        }
        __syncthreads();

        // --- phase B: zeta + wavefield update on owned rows ---
        if (act) {
            float q0 = s_w[rb + 2][cc];
            float q1 = s_w[rb + 3][cc];
            float q2 = s_w[rb + 4][cc];
            float q3 = s_w[rb + 5][cc];
            const int ns = s_nsrc;
            #pragma unroll
            for (int ii = 0; ii < 2; ii++) {
                if (ii < nb) {
                    int r = rb + ii;
                    float q4 = s_w[r + 6][cc];
                    float d2y = C2A*q0 + C2B*q1 + C2C*q2 + C2B*q3 + C2A*q4;
                    float d2x = C2A*s_w[r+4][cc-2] + C2B*s_w[r+4][cc-1] + C2C*q2
                              + C2B*s_w[r+4][cc+1] + C2A*s_w[r+4][cc+2];
                    float dpy = C1A*s_py[r][cc] + C1B*s_py[r+1][cc]
                              + C1C*s_py[r+3][cc] + C1D*s_py[r+4][cc];
                    float dpx = C1A*s_px[r+2][cc-2] + C1B*s_px[r+2][cc-1]
                              + C1C*s_px[r+2][cc+1] + C1D*s_px[r+2][cc+2];
                    float rA = s_aA[r + 2], rB = s_bA[r + 2];
                    float nzy = rB * zy[ii] + rA * (d2y + dpy);
                    float nzx = bxc * zx[ii] + axc * (d2x + dpx);
                    zy[ii] = nzy; zx[ii] = nzx;
                    float lap = d2y + d2x + dpy + dpx + nzy + nzx;
                    float wp = 2.0f * wc[ii] - wm[ii] + s_v2[r][cc] * lap;
                    for (int k = 0; k < ns; k++)
                        if (s_src_c[k] == c && s_src_r[k] == r)
                            wp += s_src_scale[k] * amp[s_src_idx[k] * NT + t];
                    __stcg(&wfn[(y0 + r) * NP + c], wp);
                    wm[ii] = wc[ii]; wc[ii] = wp;
                    q0 = q1; q1 = q2; q2 = q3; q3 = q4;
                }
            }
        }
        __syncthreads();

        // --- publish completion (release) ---
        if (tidl == 0) set_flag(&g_flag[bid * 32], t + 1);

        // --- record receivers owned by this strip ---
        for (int k = tidl; k < s_nrec; k += NTHR)
            out[s_rec_out[k] + t] = __ldcg(&wfn[(y0 + s_rec_r[k]) * NP + s_rec_c[k]]);
    }
}

// ---------------- launch ----------------
extern "C" void kernel_launch(void* const* d_in, const int* in_sizes, int n_in,
                              void* d_out, int out_size)
{
    const float* v   = (const float*)d_in[0];
    const float* amp = (const float*)d_in[1];
    const int*   sl  = (const int*)d_in[2];
    const int*   rl  = (const int*)d_in[3];

    init_all<<<NCTA, 256>>>(v, sl, rl);
    dim3 blk(BX, BY);
    wave_kernel<<<NCTA, blk>>>(amp, (float*)d_out);
}

// round 8
// speedup vs baseline: 2.8224x; 1.2083x over previous
#include <cuda_runtime.h>

// ---------------- problem constants ----------------
#define NYD 256
#define NXD 256
#define PML 20
#define PADW 22            // PML + FD_PAD
#define NP  300            // padded grid edge
#define NT  250
#define NSHOT 2
#define NSRC 8
#define NREC 64
#define DTC 0.0005f

// strips
#define SSTR 60            // strips per shot
#define RROW 5             // rows per strip
#define NCTA (NSHOT * SSTR)   // 120 CTAs (<=148 SMs -> all resident, spin-sync safe)
#define BX 160             // one thread = one column PAIR (2*tid, 2*tid+1)
#define BY 5
#define NTHR (BX*BY)       // 800 threads, 25 warps
#define NPX (NP + 4)       // 304, even -> float2-aligned rows

// FD coefficients folded with 1/h and 1/h^2 (h = 5)
#define C1A ( 1.0f/60.0f)
#define C1B (-2.0f/15.0f)
#define C1C ( 2.0f/15.0f)
#define C1D (-1.0f/60.0f)
#define C2A (-1.0f/300.0f)
#define C2B ( 4.0f/75.0f)
#define C2C (-0.1f)

// ---------------- persistent device state ----------------
__device__ float g_wf  [2][NSHOT][NP][NP];
__device__ float g_v2dt2[NP][NP];
__device__ float g_a[NP], g_b[NP];
__device__ int   g_sy[NSHOT*NSRC], g_sx[NSHOT*NSRC];
__device__ float g_sscale[NSHOT*NSRC];
__device__ int   g_ry[NSHOT*NREC], g_rx[NSHOT*NREC];
__device__ int   g_flag[NCTA * 32];          // 128B-padded flags

// ---------------- packed f32x2 helpers (FFMA2 path, sm_100+) ----------------
__device__ __forceinline__ float2 ffma2(float2 a, float2 b, float2 c) {
    float2 d;
    asm("{\n\t.reg .b64 A,B,C,D;\n\t"
        "mov.b64 A,{%2,%3};\n\tmov.b64 B,{%4,%5};\n\tmov.b64 C,{%6,%7};\n\t"
        "fma.rn.f32x2 D,A,B,C;\n\t"
        "mov.b64 {%0,%1},D;\n\t}"
        : "=f"(d.x), "=f"(d.y)
        : "f"(a.x), "f"(a.y), "f"(b.x), "f"(b.y), "f"(c.x), "f"(c.y));
    return d;
}
__device__ __forceinline__ float2 fmul2(float2 a, float2 b) {
    float2 d;
    asm("{\n\t.reg .b64 A,B,D;\n\t"
        "mov.b64 A,{%2,%3};\n\tmov.b64 B,{%4,%5};\n\t"
        "mul.rn.f32x2 D,A,B;\n\t"
        "mov.b64 {%0,%1},D;\n\t}"
        : "=f"(d.x), "=f"(d.y)
        : "f"(a.x), "f"(a.y), "f"(b.x), "f"(b.y));
    return d;
}
__device__ __forceinline__ float2 fadd2(float2 a, float2 b) {
    float2 d;
    asm("{\n\t.reg .b64 A,B,D;\n\t"
        "mov.b64 A,{%2,%3};\n\tmov.b64 B,{%4,%5};\n\t"
        "add.rn.f32x2 D,A,B;\n\t"
        "mov.b64 {%0,%1},D;\n\t}"
        : "=f"(d.x), "=f"(d.y)
        : "f"(a.x), "f"(a.y), "f"(b.x), "f"(b.y));
    return d;
}
__device__ __forceinline__ float2 bc(float s) { return make_float2(s, s); }
__device__ __forceinline__ float2 ld2s(const float* p) { return *(const float2*)p; }
__device__ __forceinline__ void   st2s(float* p, float2 v) { *(float2*)p = v; }
__device__ __forceinline__ float2 ldg2cg(const float* p) {
    float2 v;
    asm volatile("ld.global.cg.v2.f32 {%0,%1}, [%2];" : "=f"(v.x), "=f"(v.y) : "l"(p));
    return v;
}
__device__ __forceinline__ void stg2cg(float* p, float2 v) {
    asm volatile("st.global.cg.v2.f32 [%0], {%1,%2};" :: "l"(p), "f"(v.x), "f"(v.y) : "memory");
}

// ---------------- scoped sync helpers ----------------
__device__ __forceinline__ int poll_flag(const int* p) {
    int v; asm volatile("ld.acquire.gpu.b32 %0, [%1];" : "=r"(v) : "l"(p)); return v;
}
__device__ __forceinline__ void set_flag(int* p, int v) {
    asm volatile("st.release.gpu.b32 [%0], %1;" :: "l"(p), "r"(v) : "memory");
}

// ---------------- init kernel (single launch) ----------------
__global__ void init_all(const float* __restrict__ v,
                         const int* __restrict__ sl, const int* __restrict__ rl)
{
    int idx = blockIdx.x * blockDim.x + threadIdx.x;
    int stride = gridDim.x * blockDim.x;

    float* wf = &g_wf[0][0][0][0];
    const int NSTATE = 2 * NSHOT * NP * NP;
    for (int i = idx; i < NSTATE; i += stride) wf[i] = 0.f;

    for (int i = idx; i < NP * NP; i += stride) {
        int y = i / NP, x = i - y * NP;
        int vy = min(max(y - PADW, 0), NYD - 1);
        int vx = min(max(x - PADW, 0), NXD - 1);
        float vv = v[vy * NXD + vx];
        (&g_v2dt2[0][0])[i] = vv * vv * (DTC * DTC);
    }

    for (int i = idx; i < NP; i += stride) {
        double fi = (double)i;
        double frac = fmax(22.0 - fi, fi - 277.0) / (double)PML;
        frac = fmin(fmax(frac, 0.0), 1.0);
        double sm   = 3.0 * 4000.0 * log(1000.0) / (2.0 * PML * 5.0);
        double sig  = sm * frac * frac;
        double alp  = 3.141592653589793 * 25.0 * (1.0 - frac);
        double bb   = exp(-(sig + alp) * (double)DTC);
        double aa   = sig / (sig + alp + 1e-9) * (bb - 1.0);
        g_a[i] = (float)aa;
        g_b[i] = (float)bb;
    }

    for (int i = idx; i < NCTA * 32; i += stride) g_flag[i] = 0;

    if (idx == 0) {
        // int64 vs int32 detect: int64-LE viewed as int32 -> odd words all zero.
        bool s64 = true;
        for (int k = 1; k < NSHOT * NSRC * 2; k += 2) if (sl[k] != 0) { s64 = false; break; }
        for (int s = 0; s < NSHOT * NSRC; s++) {
            int y = s64 ? sl[4*s]     : sl[2*s];
            int x = s64 ? sl[4*s + 2] : sl[2*s + 1];
            g_sy[s] = y + PADW; g_sx[s] = x + PADW;
            float vv = v[y * NXD + x];
            g_sscale[s] = vv * vv * (DTC * DTC);
        }
        bool r64 = true;
        for (int k = 1; k < NSHOT * NREC * 2; k += 2) if (rl[k] != 0) { r64 = false; break; }
        for (int s = 0; s < NSHOT * NREC; s++) {
            int y = r64 ? rl[4*s]     : rl[2*s];
            int x = r64 ? rl[4*s + 2] : rl[2*s + 1];
            g_ry[s] = y + PADW; g_rx[s] = x + PADW;
        }
    }
}

// ---------------- persistent wave kernel ----------------
// Block (160, 5); each thread owns columns (2*tid, 2*tid+1).
// Phase A psi rows j (y = y0-2+j): ty0: j0,1  ty1: j2,3  ty2: j4,5  ty3: j6,7  ty4: j8
// Phase B strip row r = ty (one row each).
// Staging halo: ty0: wrows 0,1  ty1: 2,3  ty2: 9,10  ty3: 11,12 ; each ty stores own wc.
// Polls: ty0/ty1 -> top neighbor; ty2/ty3 -> bottom neighbor (acquire precedes own LDGs).
__global__ void __launch_bounds__(NTHR, 1)
wave_kernel(const float* __restrict__ amp, float* __restrict__ out)
{
    const int bid   = blockIdx.x;
    const int shot  = bid / SSTR;
    const int strip = bid - shot * SSTR;
    const int y0    = strip * RROW;
    const int tid   = threadIdx.x;
    const int ty    = threadIdx.y;
    const int tidl  = threadIdx.x + BX * threadIdx.y;
    const int c0    = 2 * tid;
    const bool act  = (c0 < NP);
    const int cc    = c0 + 2;          // even -> float2-aligned smem index

    const int jb = ty * 2;             // first psi row (ty4: j8 only)
    const int na = (ty == 4) ? 1 : 2;
    const int r  = ty;                 // phase-B strip row

    __shared__ float s_w [13][NPX];    // wf rows y0-4 .. y0+8
    __shared__ float s_py[9][NPX];     // psi rows y0-2 .. y0+6
    __shared__ float s_px[9][NPX];
    __shared__ float s_aA[9], s_bA[9];
    __shared__ int   s_nsrc, s_nrec;
    __shared__ int   s_src_r[NSRC], s_src_c[NSRC], s_src_idx[NSRC];
    __shared__ float s_src_scale[NSRC];
    __shared__ short s_rec_r[NREC], s_rec_c[NREC];
    __shared__ int   s_rec_out[NREC];

    // zero guard columns (Dirichlet boundary in x): cols 0,1 and 302,303
    if (tidl < 13) { s_w[tidl][0] = 0.f; s_w[tidl][1] = 0.f; s_w[tidl][NP+2] = 0.f; s_w[tidl][NP+3] = 0.f; }
    if (tidl >= 16 && tidl < 25) {
        int rr = tidl - 16;
        s_py[rr][0] = 0.f; s_py[rr][1] = 0.f; s_py[rr][NP+2] = 0.f; s_py[rr][NP+3] = 0.f;
        s_px[rr][0] = 0.f; s_px[rr][1] = 0.f; s_px[rr][NP+2] = 0.f; s_px[rr][NP+3] = 0.f;
    }
    if (tidl >= 32 && tidl < 41) {
        int j = tidl - 32;
        int y = y0 - 2 + j;
        bool in = (y >= 0 && y < NP);
        s_aA[j] = in ? g_a[y] : 0.f;
        s_bA[j] = in ? g_b[y] : 0.f;
    }

    if (tidl == 0) {
        int ns = 0;
        for (int i = 0; i < NSRC; i++) {
            int s = shot * NSRC + i;
            int rr = g_sy[s] - y0;
            if (rr >= 0 && rr < RROW) {
                s_src_r[ns] = rr; s_src_c[ns] = g_sx[s];
                s_src_idx[ns] = s; s_src_scale[ns] = g_sscale[s]; ns++;
            }
        }
        s_nsrc = ns;
        int nr = 0;
        for (int i = 0; i < NREC; i++) {
            int s = shot * NREC + i;
            int rr = g_ry[s] - y0;
            if (rr >= 0 && rr < RROW) {
                s_rec_r[nr] = (short)rr; s_rec_c[nr] = (short)g_rx[s];
                s_rec_out[nr] = s * NT; nr++;
            }
        }
        s_nrec = nr;
    }

    // per-thread register state (float2 = column pair)
    float2 wc  = {0.f,0.f};            // phase-B owned wavefield row
    float2 wm  = {0.f,0.f};
    float2 zy  = {0.f,0.f};
    float2 zx  = {0.f,0.f};
    float2 pyr[2] = {{0.f,0.f},{0.f,0.f}};   // phase-A owned psi rows
    float2 pxr[2] = {{0.f,0.f},{0.f,0.f}};
    float2 axc2 = {0.f,0.f}, bxc2 = {0.f,0.f}, v2 = {0.f,0.f};
    if (act) {
        axc2 = make_float2(g_a[c0], g_a[c0 + 1]);
        bxc2 = make_float2(g_b[c0], g_b[c0 + 1]);
        v2   = ld2s(&g_v2dt2[y0 + r][c0]);
    }
    const float2 vC1A = bc(C1A), vC1B = bc(C1B), vC1C = bc(C1C), vC1D = bc(C1D);
    const float2 vC2A = bc(C2A), vC2B = bc(C2B), vC2C = bc(C2C);

    const float* wfb[2] = { &g_wf[0][shot][0][0], &g_wf[1][shot][0][0] };
    __syncthreads();

    for (int t = 0; t < NT; t++) {
        const int p = t & 1;
        const float* __restrict__ wfcg = wfb[p];
        float* __restrict__ wfn        = (float*)wfb[1 - p];

        // --- poll + stage: acquire precedes this thread's own halo LDGs ---
        if (act) {
            if (ty <= 1) {
                if (strip > 0) {
                    const int* fp = &g_flag[(bid - 1) * 32];
                    while (poll_flag(fp) < t) { }
                }
                #pragma unroll
                for (int k = 0; k < 2; k++) {
                    int wrow = ty * 2 + k;             // 0..3
                    int y = y0 - 4 + wrow;
                    float2 hv = (y >= 0) ? ldg2cg(&wfcg[y * NP + c0]) : make_float2(0.f, 0.f);
                    st2s(&s_w[wrow][cc], hv);
                }
            } else if (ty <= 3) {
                if (strip < SSTR - 1) {
                    const int* fp = &g_flag[(bid + 1) * 32];
                    while (poll_flag(fp) < t) { }
                }
                #pragma unroll
                for (int k = 0; k < 2; k++) {
                    int wrow = 9 + (ty - 2) * 2 + k;   // 9..12
                    int y = y0 - 4 + wrow;
                    float2 hv = (y < NP) ? ldg2cg(&wfcg[y * NP + c0]) : make_float2(0.f, 0.f);
                    st2s(&s_w[wrow][cc], hv);
                }
            }
            st2s(&s_w[4 + r][cc], wc);                 // own row
        }
        __syncthreads();

        // --- phase A: psi rows j = jb .. jb+na-1 (register recursion) ---
        if (act) {
            float2 wv[6];
            #pragma unroll
            for (int k = 0; k < 6; k++)
                if (k < na + 4) wv[k] = ld2s(&s_w[jb + k][cc]);
            #pragma unroll
            for (int jj = 0; jj < 2; jj++) {
                if (jj < na) {
                    int j = jb + jj;
                    int y = y0 - 2 + j;
                    float2 pys = {0.f,0.f}, pxs = {0.f,0.f};
                    if (y >= 0 && y < NP) {
                        float2 a0 = wv[jj], a1 = wv[jj+1], M = wv[jj+2], a3 = wv[jj+3], a4 = wv[jj+4];
                        float2 dwdy = ffma2(vC1A, a0, ffma2(vC1B, a1, ffma2(vC1C, a3, fmul2(vC1D, a4))));
                        float2 L = ld2s(&s_w[j+2][cc-2]);
                        float2 R = ld2s(&s_w[j+2][cc+2]);
                        float2 vm1 = make_float2(L.y, M.x);
                        float2 vp1 = make_float2(M.y, R.x);
                        float2 dwdx = ffma2(vC1A, L, ffma2(vC1B, vm1, ffma2(vC1C, vp1, fmul2(vC1D, R))));
                        pys = ffma2(bc(s_bA[j]), pyr[jj], fmul2(bc(s_aA[j]), dwdy));
                        pxs = ffma2(bxc2, pxr[jj], fmul2(axc2, dwdx));
                    }
                    pyr[jj] = pys; pxr[jj] = pxs;
                    st2s(&s_py[j][cc], pys);
                    st2s(&s_px[j][cc], pxs);
                }
            }
        }
        __syncthreads();

        // --- phase B: zeta + wavefield update on row r = ty ---
        if (act) {
            float2 q0 = ld2s(&s_w[r+2][cc]);
            float2 q1 = ld2s(&s_w[r+3][cc]);
            float2 q2 = wc;
            float2 q3 = ld2s(&s_w[r+5][cc]);
            float2 q4 = ld2s(&s_w[r+6][cc]);
            float2 d2y = ffma2(vC2A, q0, ffma2(vC2B, q1, ffma2(vC2C, q2, ffma2(vC2B, q3, fmul2(vC2A, q4)))));

            float2 L = ld2s(&s_w[r+4][cc-2]);
            float2 R = ld2s(&s_w[r+4][cc+2]);
            float2 vm1 = make_float2(L.y, q2.x);
            float2 vp1 = make_float2(q2.y, R.x);
            float2 d2x = ffma2(vC2A, L, ffma2(vC2B, vm1, ffma2(vC2C, q2, ffma2(vC2B, vp1, fmul2(vC2A, R)))));

            float2 p0 = ld2s(&s_py[r][cc]);
            float2 p1 = ld2s(&s_py[r+1][cc]);
            float2 p3 = ld2s(&s_py[r+3][cc]);
            float2 p4 = ld2s(&s_py[r+4][cc]);
            float2 dpy = ffma2(vC1A, p0, ffma2(vC1B, p1, ffma2(vC1C, p3, fmul2(vC1D, p4))));

            float2 xL = ld2s(&s_px[r+2][cc-2]);
            float2 xM = ld2s(&s_px[r+2][cc]);
            float2 xR = ld2s(&s_px[r+2][cc+2]);
            float2 xm1 = make_float2(xL.y, xM.x);
            float2 xp1 = make_float2(xM.y, xR.x);
            float2 dpx = ffma2(vC1A, xL, ffma2(vC1B, xm1, ffma2(vC1C, xp1, fmul2(vC1D, xR))));

            float2 syv = fadd2(d2y, dpy);
            float2 sxv = fadd2(d2x, dpx);
            float2 nzy = ffma2(bc(s_bA[r+2]), zy, fmul2(bc(s_aA[r+2]), syv));
            float2 nzx = ffma2(bxc2, zx, fmul2(axc2, sxv));
            zy = nzy; zx = nzx;
            float2 lap = fadd2(fadd2(fadd2(syv, sxv), nzy), nzx);
            float2 base = make_float2(2.0f * wc.x - wm.x, 2.0f * wc.y - wm.y);
            float2 wp = ffma2(v2, lap, base);

            const int ns = s_nsrc;
            for (int k = 0; k < ns; k++) {
                if (s_src_r[k] == r && (s_src_c[k] >> 1) == tid) {
                    float add = s_src_scale[k] * amp[s_src_idx[k] * NT + t];
                    if (s_src_c[k] & 1) wp.y += add; else wp.x += add;
                }
            }
            stg2cg(&wfn[(y0 + r) * NP + c0], wp);
            wm = wc; wc = wp;
        }
        __syncthreads();

        // --- publish completion (release; barrier above orders all CTA writes) ---
        if (tidl == 0) set_flag(&g_flag[bid * 32], t + 1);

        // --- record receivers owned by this strip ---
        for (int k = tidl; k < s_nrec; k += NTHR)
            out[s_rec_out[k] + t] = __ldcg(&wfn[(y0 + s_rec_r[k]) * NP + s_rec_c[k]]);
    }
}

// ---------------- launch ----------------
extern "C" void kernel_launch(void* const* d_in, const int* in_sizes, int n_in,
                              void* d_out, int out_size)
{
    const float* v   = (const float*)d_in[0];
    const float* amp = (const float*)d_in[1];
    const int*   sl  = (const int*)d_in[2];
    const int*   rl  = (const int*)d_in[3];

    init_all<<<NCTA, 256>>>(v, sl, rl);
    dim3 blk(BX, BY);
    wave_kernel<<<NCTA, blk>>>(amp, (float*)d_out);
}

// round 9
// speedup vs baseline: 2.9052x; 1.0293x over previous
#include <cuda_runtime.h>

// ---------------- problem constants ----------------
#define NYD 256
#define NXD 256
#define PML 20
#define PADW 22            // PML + FD_PAD
#define NP  300            // padded grid edge
#define NT  250
#define NSHOT 2
#define NSRC 8
#define NREC 64
#define DTC 0.0005f

// strips
#define SSTR 60            // strips per shot
#define RROW 5             // rows per strip
#define NCTA (NSHOT * SSTR)   // 120 CTAs (<=148 SMs -> all resident, spin-sync safe)
#define BX 160             // one thread = one column PAIR (2*tid, 2*tid+1)
#define BY 5
#define NTHR (BX*BY)       // 800 threads, 25 warps
#define NPX (NP + 8)       // 308: 4 guard columns each side, float2-aligned

// FD coefficients folded with 1/h and 1/h^2 (h = 5)
#define C1A ( 1.0f/60.0f)
#define C1B (-2.0f/15.0f)
#define C1C ( 2.0f/15.0f)
#define C1D (-1.0f/60.0f)
#define C2A (-1.0f/300.0f)
#define C2B ( 4.0f/75.0f)
#define C2C (-0.1f)

// ---------------- persistent device state ----------------
__device__ float g_wf  [2][NSHOT][NP][NP];
__device__ float g_v2dt2[NP][NP];
__device__ float g_a[NP], g_b[NP];
__device__ int   g_sy[NSHOT*NSRC], g_sx[NSHOT*NSRC];
__device__ float g_sscale[NSHOT*NSRC];
__device__ int   g_ry[NSHOT*NREC], g_rx[NSHOT*NREC];
__device__ int   g_flag[NCTA * 32];          // 128B-padded flags

// ---------------- packed f32x2 helpers ----------------
__device__ __forceinline__ float2 ffma2(float2 a, float2 b, float2 c) {
    float2 d;
    asm("{\n\t.reg .b64 A,B,C,D;\n\t"
        "mov.b64 A,{%2,%3};\n\tmov.b64 B,{%4,%5};\n\tmov.b64 C,{%6,%7};\n\t"
        "fma.rn.f32x2 D,A,B,C;\n\t"
        "mov.b64 {%0,%1},D;\n\t}"
        : "=f"(d.x), "=f"(d.y)
        : "f"(a.x), "f"(a.y), "f"(b.x), "f"(b.y), "f"(c.x), "f"(c.y));
    return d;
}
__device__ __forceinline__ float2 fmul2(float2 a, float2 b) {
    float2 d;
    asm("{\n\t.reg .b64 A,B,D;\n\t"
        "mov.b64 A,{%2,%3};\n\tmov.b64 B,{%4,%5};\n\t"
        "mul.rn.f32x2 D,A,B;\n\t"
        "mov.b64 {%0,%1},D;\n\t}"
        : "=f"(d.x), "=f"(d.y)
        : "f"(a.x), "f"(a.y), "f"(b.x), "f"(b.y));
    return d;
}
__device__ __forceinline__ float2 fadd2(float2 a, float2 b) {
    float2 d;
    asm("{\n\t.reg .b64 A,B,D;\n\t"
        "mov.b64 A,{%2,%3};\n\tmov.b64 B,{%4,%5};\n\t"
        "add.rn.f32x2 D,A,B;\n\t"
        "mov.b64 {%0,%1},D;\n\t}"
        : "=f"(d.x), "=f"(d.y)
        : "f"(a.x), "f"(a.y), "f"(b.x), "f"(b.y));
    return d;
}
__device__ __forceinline__ float2 bc(float s) { return make_float2(s, s); }
__device__ __forceinline__ float2 sh(float2 a, float2 b) { return make_float2(a.y, b.x); }
__device__ __forceinline__ float2 ld2s(const float* p) { return *(const float2*)p; }
__device__ __forceinline__ void   st2s(float* p, float2 v) { *(float2*)p = v; }
__device__ __forceinline__ float2 ldg2cg(const float* p) {
    float2 v;
    asm volatile("ld.global.cg.v2.f32 {%0,%1}, [%2];" : "=f"(v.x), "=f"(v.y) : "l"(p));
    return v;
}
__device__ __forceinline__ void stg2cg(float* p, float2 v) {
    asm volatile("st.global.cg.v2.f32 [%0], {%1,%2};" :: "l"(p), "f"(v.x), "f"(v.y) : "memory");
}

// ---------------- scoped sync helpers ----------------
__device__ __forceinline__ int poll_flag(const int* p) {
    int v; asm volatile("ld.acquire.gpu.b32 %0, [%1];" : "=r"(v) : "l"(p)); return v;
}
__device__ __forceinline__ void set_flag(int* p, int v) {
    asm volatile("st.release.gpu.b32 [%0], %1;" :: "l"(p), "r"(v) : "memory");
}
#define BAR_ARRIVE(id) asm volatile("bar.arrive %0, %1;" :: "r"(id), "r"(NTHR) : "memory")
#define BAR_SYNCN(id)  asm volatile("bar.sync %0, %1;"   :: "r"(id), "r"(NTHR) : "memory")

// ---------------- init kernel ----------------
__global__ void init_all(const float* __restrict__ v,
                         const int* __restrict__ sl, const int* __restrict__ rl)
{
    int idx = blockIdx.x * blockDim.x + threadIdx.x;
    int stride = gridDim.x * blockDim.x;

    float* wf = &g_wf[0][0][0][0];
    const int NSTATE = 2 * NSHOT * NP * NP;
    for (int i = idx; i < NSTATE; i += stride) wf[i] = 0.f;

    for (int i = idx; i < NP * NP; i += stride) {
        int y = i / NP, x = i - y * NP;
        int vy = min(max(y - PADW, 0), NYD - 1);
        int vx = min(max(x - PADW, 0), NXD - 1);
        float vv = v[vy * NXD + vx];
        (&g_v2dt2[0][0])[i] = vv * vv * (DTC * DTC);
    }

    for (int i = idx; i < NP; i += stride) {
        double fi = (double)i;
        double frac = fmax(22.0 - fi, fi - 277.0) / (double)PML;
        frac = fmin(fmax(frac, 0.0), 1.0);
        double sm   = 3.0 * 4000.0 * log(1000.0) / (2.0 * PML * 5.0);
        double sig  = sm * frac * frac;
        double alp  = 3.141592653589793 * 25.0 * (1.0 - frac);
        double bb   = exp(-(sig + alp) * (double)DTC);
        double aa   = sig / (sig + alp + 1e-9) * (bb - 1.0);
        g_a[i] = (float)aa;
        g_b[i] = (float)bb;
    }

    for (int i = idx; i < NCTA * 32; i += stride) g_flag[i] = 0;

    if (idx == 0) {
        bool s64 = true;
        for (int k = 1; k < NSHOT * NSRC * 2; k += 2) if (sl[k] != 0) { s64 = false; break; }
        for (int s = 0; s < NSHOT * NSRC; s++) {
            int y = s64 ? sl[4*s]     : sl[2*s];
            int x = s64 ? sl[4*s + 2] : sl[2*s + 1];
            g_sy[s] = y + PADW; g_sx[s] = x + PADW;
            float vv = v[y * NXD + x];
            g_sscale[s] = vv * vv * (DTC * DTC);
        }
        bool r64 = true;
        for (int k = 1; k < NSHOT * NREC * 2; k += 2) if (rl[k] != 0) { r64 = false; break; }
        for (int s = 0; s < NSHOT * NREC; s++) {
            int y = r64 ? rl[4*s]     : rl[2*s];
            int x = r64 ? rl[4*s + 2] : rl[2*s + 1];
            g_ry[s] = y + PADW; g_rx[s] = x + PADW;
        }
    }
}

// ---------------- persistent wave kernel (fully fused, 1 barrier/step) ----------------
// Block (160, 5); thread = (row r = ty, columns c0=2*tid, c0+1).
// Register-private psi: psi_y at rows r-2..r+2, psi_x at pairs c0-2, c0, c0+2.
__global__ void __launch_bounds__(NTHR, 1)
wave_kernel(const float* __restrict__ amp, float* __restrict__ out)
{
    const int bid   = blockIdx.x;
    const int shot  = bid / SSTR;
    const int strip = bid - shot * SSTR;
    const int y0    = strip * RROW;
    const int tid   = threadIdx.x;
    const int r     = threadIdx.y;
    const int tidl  = threadIdx.x + BX * threadIdx.y;
    const int c0    = 2 * tid;
    const bool act  = (c0 < NP);
    const int cc    = c0 + 4;           // float2-aligned (even)

    __shared__ float s_w[2][13][NPX];   // double-buffered wf rows y0-4 .. y0+8
    __shared__ float s_axp[NPX], s_bxp[NPX];   // x-direction PML profiles (guard-padded)
    __shared__ float s_aA[9], s_bA[9];         // y-profile rows y0-2 .. y0+6
    __shared__ int   s_nsrc, s_nrec;
    __shared__ int   s_src_r[NSRC], s_src_c[NSRC], s_src_idx[NSRC];
    __shared__ float s_src_scale[NSRC];
    __shared__ short s_rec_r[NREC], s_rec_c[NREC];
    __shared__ int   s_rec_out[NREC];

    // zero guard columns in BOTH buffers (cols 0..3 and NP+4..NP+7)
    if (tidl < 26) {
        int b = tidl / 13, row = tidl % 13;
        #pragma unroll
        for (int g = 0; g < 4; g++) {
            s_w[b][row][g] = 0.f;
            s_w[b][row][NP + 4 + g] = 0.f;
        }
    }
    // x profiles with zero guards
    for (int i = tidl; i < NPX; i += NTHR) {
        int col = i - 4;
        bool in = (col >= 0 && col < NP);
        s_axp[i] = in ? g_a[col] : 0.f;
        s_bxp[i] = in ? g_b[col] : 0.f;
    }
    if (tidl >= 32 && tidl < 41) {
        int j = tidl - 32;
        int y = y0 - 2 + j;
        bool in = (y >= 0 && y < NP);
        s_aA[j] = in ? g_a[y] : 0.f;
        s_bA[j] = in ? g_b[y] : 0.f;
    }
    if (tidl == 0) {
        int ns = 0;
        for (int i = 0; i < NSRC; i++) {
            int s = shot * NSRC + i;
            int rr = g_sy[s] - y0;
            if (rr >= 0 && rr < RROW) {
                s_src_r[ns] = rr; s_src_c[ns] = g_sx[s];
                s_src_idx[ns] = s; s_src_scale[ns] = g_sscale[s]; ns++;
            }
        }
        s_nsrc = ns;
        int nr = 0;
        for (int i = 0; i < NREC; i++) {
            int s = shot * NREC + i;
            int rr = g_ry[s] - y0;
            if (rr >= 0 && rr < RROW) {
                s_rec_r[nr] = (short)rr; s_rec_c[nr] = (short)g_rx[s];
                s_rec_out[nr] = s * NT; nr++;
            }
        }
        s_nrec = nr;
    }

    // ---- per-thread register state ----
    float2 wc = {0.f,0.f}, wm = {0.f,0.f};
    float2 zy = {0.f,0.f}, zx = {0.f,0.f};
    float2 pyr[5] = {{0.f,0.f},{0.f,0.f},{0.f,0.f},{0.f,0.f},{0.f,0.f}};
    float2 pxL = {0.f,0.f}, pxM = {0.f,0.f}, pxR = {0.f,0.f};
    float2 v2 = {0.f,0.f}, axM = {0.f,0.f}, bxM = {0.f,0.f};
    if (act) {
        v2  = ld2s(&g_v2dt2[y0 + r][c0]);
        axM = make_float2(g_a[c0], g_a[c0 + 1]);
        bxM = make_float2(g_b[c0], g_b[c0 + 1]);
    }
    const float2 vC1A = bc(C1A), vC1B = bc(C1B), vC1C = bc(C1C), vC1D = bc(C1D);
    const float2 vC2A = bc(C2A), vC2B = bc(C2B), vC2C = bc(C2C);

    const float* wfb[2] = { &g_wf[0][shot][0][0], &g_wf[1][shot][0][0] };
    __syncthreads();

    for (int t = 0; t < NT; t++) {
        const int p = t & 1;
        const float* __restrict__ wfcg = wfb[p];
        float* __restrict__ wfn        = (float*)wfb[1 - p];
        float (* __restrict__ sw)[NPX] = s_w[p];

        // ---- staging into buffer p (other buffer untouched by readers) ----
        if (act) {
            if (r <= 1) {                 // top halo rows 0..3 (y = y0-4 .. y0-1)
                if (strip > 0) {
                    const int* fp = &g_flag[(bid - 1) * 32];
                    while (poll_flag(fp) < t) { }
                }
                #pragma unroll
                for (int k = 0; k < 2; k++) {
                    int wrow = r * 2 + k;
                    int y = y0 - 4 + wrow;
                    float2 hv = (y >= 0) ? ldg2cg(&wfcg[y * NP + c0]) : make_float2(0.f, 0.f);
                    st2s(&sw[wrow][cc], hv);
                }
            } else if (r <= 3) {          // bottom halo rows 9..12 (y = y0+5 .. y0+8)
                if (strip < SSTR - 1) {
                    const int* fp = &g_flag[(bid + 1) * 32];
                    while (poll_flag(fp) < t) { }
                }
                #pragma unroll
                for (int k = 0; k < 2; k++) {
                    int wrow = 9 + (r - 2) * 2 + k;
                    int y = y0 - 4 + wrow;
                    float2 hv = (y < NP) ? ldg2cg(&wfcg[y * NP + c0]) : make_float2(0.f, 0.f);
                    st2s(&sw[wrow][cc], hv);
                }
            }
            st2s(&sw[4 + r][cc], wc);     // own row
        }
        __syncthreads();

        // ---- record receivers of previous step (off the critical tail) ----
        if (t > 0) {
            for (int k = tidl; k < s_nrec; k += NTHR)
                out[s_rec_out[k] + (t - 1)] =
                    __ldcg(&wfcg[(y0 + s_rec_r[k]) * NP + s_rec_c[k]]);
        }

        // ---- fused compute: psi (registers) + zeta + wavefield ----
        if (act) {
            // wf column regs: rows r..r+8 of s_w (y = y0+r-4 .. y0+r+4)
            float2 w0 = ld2s(&sw[r + 0][cc]);
            float2 w1 = ld2s(&sw[r + 1][cc]);
            float2 w2 = ld2s(&sw[r + 2][cc]);
            float2 w3 = ld2s(&sw[r + 3][cc]);
            float2 w4 = wc;
            float2 w5 = ld2s(&sw[r + 5][cc]);
            float2 w6 = ld2s(&sw[r + 6][cc]);
            float2 w7 = ld2s(&sw[r + 7][cc]);
            float2 w8 = ld2s(&sw[r + 8][cc]);

            // psi_y recursion at 5 rows (m=0..4 <-> y = y0+r-2+m)
            {
                float2 d;
                d = ffma2(vC1A, w0, ffma2(vC1B, w1, ffma2(vC1C, w3, fmul2(vC1D, w4))));
                pyr[0] = ffma2(bc(s_bA[r + 0]), pyr[0], fmul2(bc(s_aA[r + 0]), d));
                d = ffma2(vC1A, w1, ffma2(vC1B, w2, ffma2(vC1C, w4, fmul2(vC1D, w5))));
                pyr[1] = ffma2(bc(s_bA[r + 1]), pyr[1], fmul2(bc(s_aA[r + 1]), d));
                d = ffma2(vC1A, w2, ffma2(vC1B, w3, ffma2(vC1C, w5, fmul2(vC1D, w6))));
                pyr[2] = ffma2(bc(s_bA[r + 2]), pyr[2], fmul2(bc(s_aA[r + 2]), d));
                d = ffma2(vC1A, w3, ffma2(vC1B, w4, ffma2(vC1C, w6, fmul2(vC1D, w7))));
                pyr[3] = ffma2(bc(s_bA[r + 3]), pyr[3], fmul2(bc(s_aA[r + 3]), d));
                d = ffma2(vC1A, w4, ffma2(vC1B, w5, ffma2(vC1C, w7, fmul2(vC1D, w8))));
                pyr[4] = ffma2(bc(s_bA[r + 4]), pyr[4], fmul2(bc(s_aA[r + 4]), d));
            }

            // x-row loads at own row (s_w row r+4)
            float2 XL2 = ld2s(&sw[r + 4][cc - 4]);
            float2 XL  = ld2s(&sw[r + 4][cc - 2]);
            float2 XM  = w4;
            float2 XR  = ld2s(&sw[r + 4][cc + 2]);
            float2 XR2 = ld2s(&sw[r + 4][cc + 4]);
            float2 s1 = sh(XL2, XL), s2 = sh(XL, XM), s3 = sh(XM, XR), s4 = sh(XR, XR2);

            // psi_x recursion at 3 column pairs
            {
                float2 axL = ld2s(&s_axp[cc - 2]), bxL = ld2s(&s_bxp[cc - 2]);
                float2 axR = ld2s(&s_axp[cc + 2]), bxR = ld2s(&s_bxp[cc + 2]);
                float2 d;
                d = ffma2(vC1A, XL2, ffma2(vC1B, s1, ffma2(vC1C, s2, fmul2(vC1D, XM))));
                pxL = ffma2(bxL, pxL, fmul2(axL, d));
                d = ffma2(vC1A, XL, ffma2(vC1B, s2, ffma2(vC1C, s3, fmul2(vC1D, XR))));
                pxM = ffma2(bxM, pxM, fmul2(axM, d));
                d = ffma2(vC1A, XM, ffma2(vC1B, s3, ffma2(vC1C, s4, fmul2(vC1D, XR2))));
                pxR = ffma2(bxR, pxR, fmul2(axR, d));
            }

            // stencils on own row
            float2 d2y = ffma2(vC2A, w2, ffma2(vC2B, w3, ffma2(vC2C, w4,
                         ffma2(vC2B, w5, fmul2(vC2A, w6)))));
            float2 d2x = ffma2(vC2A, XL, ffma2(vC2B, s2, ffma2(vC2C, XM,
                         ffma2(vC2B, s3, fmul2(vC2A, XR)))));
            float2 dpy = ffma2(vC1A, pyr[0], ffma2(vC1B, pyr[1],
                         ffma2(vC1C, pyr[3], fmul2(vC1D, pyr[4]))));
            float2 dpx = ffma2(vC1A, pxL, ffma2(vC1B, sh(pxL, pxM),
                         ffma2(vC1C, sh(pxM, pxR), fmul2(vC1D, pxR))));

            float2 syv = fadd2(d2y, dpy);
            float2 sxv = fadd2(d2x, dpx);
            float2 nzy = ffma2(bc(s_bA[r + 2]), zy, fmul2(bc(s_aA[r + 2]), syv));
            float2 nzx = ffma2(bxM, zx, fmul2(axM, sxv));
            zy = nzy; zx = nzx;
            float2 lap = fadd2(fadd2(fadd2(syv, sxv), nzy), nzx);
            float2 base = make_float2(2.0f * wc.x - wm.x, 2.0f * wc.y - wm.y);
            float2 wp = ffma2(v2, lap, base);

            const int ns = s_nsrc;
            for (int k = 0; k < ns; k++) {
                if (s_src_r[k] == r && (s_src_c[k] >> 1) == tid) {
                    float add = s_src_scale[k] * amp[s_src_idx[k] * NT + t];
                    if (s_src_c[k] & 1) wp.y += add; else wp.x += add;
                }
            }
            stg2cg(&wfn[(y0 + r) * NP + c0], wp);
            wm = wc; wc = wp;
        }

        // ---- completion: warps 1..24 arrive and move on; warp 0 syncs + flags ----
        if (tidl < 32) {
            BAR_SYNCN(1);
            if (tidl == 0) set_flag(&g_flag[bid * 32], t + 1);
        } else {
            BAR_ARRIVE(1);
        }
    }

    // final receiver recording for step NT-1
    __syncthreads();
    {
        const float* wfl = wfb[NT & 1];
        for (int k = tidl; k < s_nrec; k += NTHR)
            out[s_rec_out[k] + (NT - 1)] =
                __ldcg(&wfl[(y0 + s_rec_r[k]) * NP + s_rec_c[k]]);
    }
}

// ---------------- launch ----------------
extern "C" void kernel_launch(void* const* d_in, const int* in_sizes, int n_in,
                              void* d_out, int out_size)
{
    const float* v   = (const float*)d_in[0];
    const float* amp = (const float*)d_in[1];
    const int*   sl  = (const int*)d_in[2];
    const int*   rl  = (const int*)d_in[3];

    init_all<<<NCTA, 256>>>(v, sl, rl);
    dim3 blk(BX, BY);
    wave_kernel<<<NCTA, blk>>>(amp, (float*)d_out);
}